// round 1
// baseline (speedup 1.0000x reference)
#include <cuda_runtime.h>
#include <math.h>

#define B_  256
#define T_  500
#define BT_ 128000
#define DK_ 128
#define DV_ 256
#define M_  50
#define KF_ 384   // DV + DK

// ---------------- scratch (static device allocations; no cudaMalloc) ----------------
__device__ float g_E[(size_t)BT_ * DV_];     // sigmoid(qa@We^T+be)
__device__ float g_A[(size_t)BT_ * DV_];     // tanh(qa@Wa^T+ba)
__device__ float g_Wt[(size_t)BT_ * M_];     // logits -> softmax weights
__device__ float g_FEAT[(size_t)BT_ * KF_];  // [reads | q_e]
__device__ float g_part[2 * (BT_ / 128)];    // per-block (loss_sum, valid_count)

// ---------------- generic fp32 tiled GEMM with row-gather A  ----------------
// C[r][n] = act( sum_k tab[idx[r]][k] * Wm[n][k] + bias[n] )
template <int BM, int BN, int BK, int TM, int TN, int ACT, bool VEC>
__global__ void __launch_bounds__((BM / TM) * (BN / TN)) sgemm_gather(
    const float* __restrict__ tab, const int* __restrict__ idx,
    const float* __restrict__ Wm, const float* __restrict__ bias,
    float* __restrict__ out, int ldOut, int N, int K) {
  constexpr int THREADS = (BM / TM) * (BN / TN);
  constexpr int TX = BN / TN;
  constexpr int AV = (BM * BK) / (4 * THREADS);
  constexpr int BV = (BN * BK) / (4 * THREADS);
  static_assert(AV >= 1 && BV >= 1, "tile too small");

  __shared__ float As[BK][BM];
  __shared__ float Bs[BK][BN];
  __shared__ int rowIdx[BM];

  const int tid = threadIdx.x;
  const int bm = blockIdx.y * BM;
  const int bn = blockIdx.x * BN;

  for (int i = tid; i < BM; i += THREADS)
    rowIdx[i] = idx ? idx[bm + i] : (bm + i);
  __syncthreads();

  float acc[TM][TN];
#pragma unroll
  for (int i = 0; i < TM; i++)
#pragma unroll
    for (int j = 0; j < TN; j++) acc[i][j] = 0.f;

  const int tx = tid % TX;
  const int ty = tid / TX;

  for (int k0 = 0; k0 < K; k0 += BK) {
#pragma unroll
    for (int v = 0; v < AV; v++) {
      int f = tid + v * THREADS;
      int i = f / (BK / 4);
      int kv = f % (BK / 4);
      float4 a4 = *(const float4*)(tab + (size_t)rowIdx[i] * K + k0 + kv * 4);
      As[kv * 4 + 0][i] = a4.x;
      As[kv * 4 + 1][i] = a4.y;
      As[kv * 4 + 2][i] = a4.z;
      As[kv * 4 + 3][i] = a4.w;
    }
#pragma unroll
    for (int v = 0; v < BV; v++) {
      int f = tid + v * THREADS;
      int n = f / (BK / 4);
      int kv = f % (BK / 4);
      float4 b4 = make_float4(0.f, 0.f, 0.f, 0.f);
      if (bn + n < N) b4 = *(const float4*)(Wm + (size_t)(bn + n) * K + k0 + kv * 4);
      Bs[kv * 4 + 0][n] = b4.x;
      Bs[kv * 4 + 1][n] = b4.y;
      Bs[kv * 4 + 2][n] = b4.z;
      Bs[kv * 4 + 3][n] = b4.w;
    }
    __syncthreads();
#pragma unroll
    for (int kk = 0; kk < BK; kk++) {
      float ar[TM], br[TN];
#pragma unroll
      for (int i4 = 0; i4 < TM; i4 += 4) {
        float4 t4 = *(const float4*)(&As[kk][ty * TM + i4]);
        ar[i4 + 0] = t4.x; ar[i4 + 1] = t4.y; ar[i4 + 2] = t4.z; ar[i4 + 3] = t4.w;
      }
#pragma unroll
      for (int j4 = 0; j4 < TN; j4 += 4) {
        float4 t4 = *(const float4*)(&Bs[kk][tx * TN + j4]);
        br[j4 + 0] = t4.x; br[j4 + 1] = t4.y; br[j4 + 2] = t4.z; br[j4 + 3] = t4.w;
      }
#pragma unroll
      for (int i = 0; i < TM; i++)
#pragma unroll
        for (int j = 0; j < TN; j++) acc[i][j] = fmaf(ar[i], br[j], acc[i][j]);
    }
    __syncthreads();
  }

  // epilogue
  if (VEC) {
    float bb[TN];
#pragma unroll
    for (int j = 0; j < TN; j++) bb[j] = bias ? bias[bn + tx * TN + j] : 0.f;
#pragma unroll
    for (int i = 0; i < TM; i++) {
      size_t r = (size_t)(bm + ty * TM + i);
#pragma unroll
      for (int j4 = 0; j4 < TN; j4 += 4) {
        float4 v;
        float t0 = acc[i][j4 + 0] + bb[j4 + 0];
        float t1 = acc[i][j4 + 1] + bb[j4 + 1];
        float t2 = acc[i][j4 + 2] + bb[j4 + 2];
        float t3 = acc[i][j4 + 3] + bb[j4 + 3];
        if (ACT == 0) {
          t0 = 1.f / (1.f + expf(-t0)); t1 = 1.f / (1.f + expf(-t1));
          t2 = 1.f / (1.f + expf(-t2)); t3 = 1.f / (1.f + expf(-t3));
        } else if (ACT == 1) {
          t0 = tanhf(t0); t1 = tanhf(t1); t2 = tanhf(t2); t3 = tanhf(t3);
        }
        v.x = t0; v.y = t1; v.z = t2; v.w = t3;
        *(float4*)(out + r * ldOut + bn + tx * TN + j4) = v;
      }
    }
  } else {
#pragma unroll
    for (int i = 0; i < TM; i++) {
      size_t r = (size_t)(bm + ty * TM + i);
#pragma unroll
      for (int j = 0; j < TN; j++) {
        int n = bn + tx * TN + j;
        if (n < N) {
          float v = acc[i][j] + (bias ? bias[n] : 0.f);
          if (ACT == 0) v = 1.f / (1.f + expf(-v));
          else if (ACT == 1) v = tanhf(v);
          out[r * ldOut + n] = v;
        }
      }
    }
  }
}

// ---------------- softmax over M_=50 per row (one warp per row) ----------------
__global__ void __launch_bounds__(256) softmax_kernel() {
  int gw = (blockIdx.x * blockDim.x + threadIdx.x) >> 5;
  if (gw >= BT_) return;
  int lane = threadIdx.x & 31;
  float* w = g_Wt + (size_t)gw * M_;
  float v0 = w[lane];                                    // lane < 32 < 50
  float v1 = (lane + 32 < M_) ? w[lane + 32] : -1e30f;
  float mx = fmaxf(v0, v1);
#pragma unroll
  for (int o = 16; o; o >>= 1) mx = fmaxf(mx, __shfl_xor_sync(0xffffffffu, mx, o));
  float e0 = expf(v0 - mx);
  float e1 = (lane + 32 < M_) ? expf(v1 - mx) : 0.f;
  float s = e0 + e1;
#pragma unroll
  for (int o = 16; o; o >>= 1) s += __shfl_xor_sync(0xffffffffu, s, o);
  float inv = 1.f / s;
  w[lane] = e0 * inv;
  if (lane + 32 < M_) w[lane + 32] = e1 * inv;
}

// ---------------- gather q_e into FEAT[:, 256:384] ----------------
__global__ void __launch_bounds__(256) gatherq_kernel(
    const float* __restrict__ q_tab, const int* __restrict__ q_data) {
  int gid = blockIdx.x * blockDim.x + threadIdx.x;  // BT_*32 total
  int row = gid >> 5;
  int c = (gid & 31) << 2;
  float4 v = *(const float4*)(q_tab + (size_t)q_data[row] * DK_ + c);
  *(float4*)(g_FEAT + (size_t)row * KF_ + DV_ + c) = v;
}

// ---------------- sequential memory scan: one CTA per batch element ----------------
// Mv held in registers: thread d owns column d (50 regs). Prefetch next step's e/a/w.
__global__ void __launch_bounds__(256) scan_kernel(
    const float* __restrict__ Mv0, const int* __restrict__ q_data) {
  const int b = blockIdx.x;
  const int d = threadIdx.x;
  __shared__ float ws[2][M_];

  float mv[M_];
#pragma unroll
  for (int m = 0; m < M_; m++) mv[m] = Mv0[m * DV_ + d];

  const size_t row0 = (size_t)b * T_;
  // prologue: load t=0
  float e = g_E[row0 * DV_ + d];
  float a = g_A[row0 * DV_ + d];
  int qi = q_data[row0];
  if (d < M_) ws[0][d] = g_Wt[row0 * M_ + d];
  __syncthreads();

  int cur = 0;
  for (int t = 0; t < T_; t++) {
    size_t row = row0 + t;
    // prefetch t+1 (latency hides under compute)
    float e2 = 0.f, a2 = 0.f, w2 = 0.f;
    int qi2 = 0;
    if (t + 1 < T_) {
      size_t rn = row + 1;
      e2 = g_E[rn * DV_ + d];
      a2 = g_A[rn * DV_ + d];
      if (d < M_) w2 = g_Wt[rn * M_ + d];
      qi2 = q_data[rn];
    }

    float rd0 = 0.f, rd1 = 0.f;
    if (qi >= 1) {  // uniform across block
#pragma unroll
      for (int m = 0; m < M_; m += 2) {
        float wa = ws[cur][m], wb = ws[cur][m + 1];
        rd0 = fmaf(wa, mv[m], rd0);
        rd1 = fmaf(wb, mv[m + 1], rd1);
        float xa = wa * e, xb = wb * e;
        float ua = fmaf(-xa, mv[m], mv[m]);
        float ub = fmaf(-xb, mv[m + 1], mv[m + 1]);
        mv[m] = fmaf(wa, a, ua);
        mv[m + 1] = fmaf(wb, a, ub);
      }
    } else {
#pragma unroll
      for (int m = 0; m < M_; m += 2) {
        rd0 = fmaf(ws[cur][m], mv[m], rd0);
        rd1 = fmaf(ws[cur][m + 1], mv[m + 1], rd1);
      }
    }
    g_FEAT[row * KF_ + d] = rd0 + rd1;

    if (d < M_) ws[cur ^ 1][d] = w2;
    __syncthreads();
    e = e2; a = a2; qi = qi2; cur ^= 1;
  }
}

// ---------------- final GEMM (h = tanh(FEAT@Wr^T + br)) + fused head ----------------
__global__ void __launch_bounds__(256) final_kernel(
    const float* __restrict__ Wr, const float* __restrict__ br,
    const float* __restrict__ Wp, const float* __restrict__ bp,
    const float* __restrict__ target, float* __restrict__ out_probs) {
  constexpr int BM = 128, BN = 128, BK = 16, TM = 8, TN = 8, THREADS = 256, TX = 16;
  const int K = KF_;

  __shared__ float As[BK][BM];
  __shared__ float Bs[BK][BN];
  __shared__ float sWp[128];
  __shared__ float red[BM][17];
  __shared__ float sl[128], sv[128];

  const int tid = threadIdx.x;
  const int bm = blockIdx.y * BM;
  if (tid < 128) sWp[tid] = Wp[tid];

  float acc[TM][TN];
#pragma unroll
  for (int i = 0; i < TM; i++)
#pragma unroll
    for (int j = 0; j < TN; j++) acc[i][j] = 0.f;

  const int tx = tid % TX;
  const int ty = tid / TX;

  for (int k0 = 0; k0 < K; k0 += BK) {
#pragma unroll
    for (int v = 0; v < 2; v++) {  // BM*BK/4/THREADS = 2
      int f = tid + v * THREADS;
      int i = f / (BK / 4);
      int kv = f % (BK / 4);
      float4 a4 = *(const float4*)(g_FEAT + (size_t)(bm + i) * KF_ + k0 + kv * 4);
      As[kv * 4 + 0][i] = a4.x; As[kv * 4 + 1][i] = a4.y;
      As[kv * 4 + 2][i] = a4.z; As[kv * 4 + 3][i] = a4.w;
    }
#pragma unroll
    for (int v = 0; v < 2; v++) {
      int f = tid + v * THREADS;
      int n = f / (BK / 4);
      int kv = f % (BK / 4);
      float4 b4 = *(const float4*)(Wr + (size_t)n * K + k0 + kv * 4);
      Bs[kv * 4 + 0][n] = b4.x; Bs[kv * 4 + 1][n] = b4.y;
      Bs[kv * 4 + 2][n] = b4.z; Bs[kv * 4 + 3][n] = b4.w;
    }
    __syncthreads();
#pragma unroll
    for (int kk = 0; kk < BK; kk++) {
      float ar[TM], brg[TN];
#pragma unroll
      for (int i4 = 0; i4 < TM; i4 += 4) {
        float4 t4 = *(const float4*)(&As[kk][ty * TM + i4]);
        ar[i4 + 0] = t4.x; ar[i4 + 1] = t4.y; ar[i4 + 2] = t4.z; ar[i4 + 3] = t4.w;
      }
#pragma unroll
      for (int j4 = 0; j4 < TN; j4 += 4) {
        float4 t4 = *(const float4*)(&Bs[kk][tx * TN + j4]);
        brg[j4 + 0] = t4.x; brg[j4 + 1] = t4.y; brg[j4 + 2] = t4.z; brg[j4 + 3] = t4.w;
      }
#pragma unroll
      for (int i = 0; i < TM; i++)
#pragma unroll
        for (int j = 0; j < TN; j++) acc[i][j] = fmaf(ar[i], brg[j], acc[i][j]);
    }
    __syncthreads();
  }

  // h = tanh(acc + br), partial pred = sum_j h*Wp
  float ps[TM];
#pragma unroll
  for (int i = 0; i < TM; i++) ps[i] = 0.f;
#pragma unroll
  for (int j = 0; j < TN; j++) {
    int n = tx * TN + j;
    float bb = br[n];
    float wp = sWp[n];
#pragma unroll
    for (int i = 0; i < TM; i++) {
      float h = tanhf(acc[i][j] + bb);
      ps[i] = fmaf(h, wp, ps[i]);
    }
  }
#pragma unroll
  for (int i = 0; i < TM; i++) red[ty * TM + i][tx] = ps[i];
  __syncthreads();

  float per = 0.f, val = 0.f;
  if (tid < 128) {
    float p = bp[0];
#pragma unroll
    for (int j = 0; j < 16; j++) p += red[tid][j];
    size_t row = (size_t)bm + tid;
    out_probs[row] = 1.f / (1.f + expf(-p));
    float tg = target[row];
    if (tg >= 0.f) {
      per = fmaxf(p, 0.f) - p * tg + log1pf(expf(-fabsf(p)));
      val = 1.f;
    }
  }
  __syncthreads();
  if (tid < 128) { sl[tid] = per; sv[tid] = val; }
  __syncthreads();
  for (int s = 64; s > 0; s >>= 1) {
    if (tid < s) { sl[tid] += sl[tid + s]; sv[tid] += sv[tid + s]; }
    __syncthreads();
  }
  if (tid == 0) {
    g_part[2 * blockIdx.y] = sl[0];
    g_part[2 * blockIdx.y + 1] = sv[0];
  }
}

// ---------------- final loss reduction ----------------
__global__ void __launch_bounds__(256) finalize_kernel(float* __restrict__ out) {
  __shared__ float sl[256], sv[256];
  int tid = threadIdx.x;
  float l = 0.f, v = 0.f;
  for (int i = tid; i < BT_ / 128; i += 256) {
    l += g_part[2 * i];
    v += g_part[2 * i + 1];
  }
  sl[tid] = l; sv[tid] = v;
  __syncthreads();
  for (int s = 128; s > 0; s >>= 1) {
    if (tid < s) { sl[tid] += sl[tid + s]; sv[tid] += sv[tid + s]; }
    __syncthreads();
  }
  if (tid == 0) out[0] = sl[0] / fmaxf(sv[0], 1.f);
}

// ---------------- launch ----------------
extern "C" void kernel_launch(void* const* d_in, const int* in_sizes, int n_in,
                              void* d_out, int out_size) {
  const int* q_data = (const int*)d_in[0];
  const int* qa_data = (const int*)d_in[1];
  const float* target = (const float*)d_in[2];
  const float* q_tab = (const float*)d_in[3];
  const float* qa_tab = (const float*)d_in[4];
  const float* Mk = (const float*)d_in[5];
  const float* Mv0 = (const float*)d_in[6];
  const float* We = (const float*)d_in[7];
  const float* be = (const float*)d_in[8];
  const float* Wa = (const float*)d_in[9];
  const float* ba = (const float*)d_in[10];
  const float* Wr = (const float*)d_in[11];
  const float* br = (const float*)d_in[12];
  const float* Wp = (const float*)d_in[13];
  const float* bp = (const float*)d_in[14];
  float* out = (float*)d_out;

  float* pE; cudaGetSymbolAddress((void**)&pE, g_E);
  float* pA; cudaGetSymbolAddress((void**)&pA, g_A);
  float* pW; cudaGetSymbolAddress((void**)&pW, g_Wt);

  dim3 gEA(DV_ / 128, BT_ / 128);
  sgemm_gather<128, 128, 16, 8, 8, 0, true><<<gEA, 256>>>(
      qa_tab, qa_data, We, be, pE, DV_, DV_, DV_);
  sgemm_gather<128, 128, 16, 8, 8, 1, true><<<gEA, 256>>>(
      qa_tab, qa_data, Wa, ba, pA, DV_, DV_, DV_);
  dim3 gL(1, BT_ / 128);
  sgemm_gather<128, 64, 16, 8, 4, 2, false><<<gL, 256>>>(
      q_tab, q_data, Mk, nullptr, pW, M_, M_, DK_);
  softmax_kernel<<<BT_ / 8, 256>>>();
  gatherq_kernel<<<BT_ / 8, 256>>>(q_tab, q_data);
  scan_kernel<<<B_, 256>>>(Mv0, q_data);
  final_kernel<<<dim3(1, BT_ / 128), 256>>>(Wr, br, Wp, bp, target, out + 1);
  finalize_kernel<<<1, 256>>>(out);
}

// round 2
// speedup vs baseline: 1.7722x; 1.7722x over previous
#include <cuda_runtime.h>
#include <math.h>

#define B_  256
#define T_  500
#define BT_ 128000
#define DK_ 128
#define DV_ 256
#define M_  50
#define KF_ 384   // DV + DK

// ---------------- scratch ----------------
__device__ float g_E[(size_t)BT_ * DV_];
__device__ float g_A[(size_t)BT_ * DV_];
__device__ float g_Wt[(size_t)BT_ * M_];
__device__ float g_FEAT[(size_t)BT_ * KF_];
__device__ float g_part[2 * (BT_ / 128)];

// ---------------- helpers ----------------
__device__ __forceinline__ unsigned cvt_tf32(float x) {
  unsigned u;
  asm("cvt.rna.tf32.f32 %0, %1;" : "=r"(u) : "f"(x));
  return u;
}

__device__ __forceinline__ void mma_tf32(float* c, const unsigned* a, const unsigned* b) {
  asm volatile(
      "mma.sync.aligned.m16n8k8.row.col.f32.tf32.tf32.f32 "
      "{%0,%1,%2,%3}, {%4,%5,%6,%7}, {%8,%9}, {%0,%1,%2,%3};\n"
      : "+f"(c[0]), "+f"(c[1]), "+f"(c[2]), "+f"(c[3])
      : "r"(a[0]), "r"(a[1]), "r"(a[2]), "r"(a[3]), "r"(b[0]), "r"(b[1]));
}

// k-permutation within each 8-chunk so a thread's fragment pair (k=c, k=c+4)
// is contiguous: pos(kl) within tile.
__host__ __device__ __forceinline__ constexpr int tpos(int kl) {
  return (kl >> 3) * 8 + 2 * (kl & 3) + ((kl & 7) >> 2);
}

__device__ __forceinline__ unsigned long long pack2(float lo, float hi) {
  unsigned long long r;
  asm("mov.b64 %0, {%1,%2};" : "=l"(r) : "f"(lo), "f"(hi));
  return r;
}
__device__ __forceinline__ unsigned long long fma2(unsigned long long a,
                                                   unsigned long long b,
                                                   unsigned long long c) {
  unsigned long long d;
  asm("fma.rn.f32x2 %0, %1, %2, %3;" : "=l"(d) : "l"(a), "l"(b), "l"(c));
  return d;
}
__device__ __forceinline__ float2 unpack2(unsigned long long v) {
  float2 f;
  asm("mov.b64 {%0,%1}, %2;" : "=f"(f.x), "=f"(f.y) : "l"(v));
  return f;
}

// ================= tf32 GEMM: E and A fused (grid.x: 0,1 -> E slabs; 2,3 -> A) ======
// C = act(gather(qa_tab, qa_data) @ W^T + bias), M=BT, N=256 per target, K=256
__global__ void __launch_bounds__(256) gemm_ea_tf32(
    const float* __restrict__ tab, const int* __restrict__ idx,
    const float* __restrict__ We, const float* __restrict__ be,
    const float* __restrict__ Wa, const float* __restrict__ ba) {
  constexpr int BM = 128, BK = 16, K = 256, KT = K / BK;
  constexpr int MT = 4, NT = 4;  // warp tile 64x32, warp grid 2x4

  __shared__ unsigned As[BM][18];
  __shared__ unsigned Bs[128][18];
  __shared__ int rowA[BM];

  const int tid = threadIdx.x;
  const int wid = tid >> 5, lane = tid & 31;
  const int wm = wid >> 2, wn = wid & 3;  // 2 x 4
  const int r = lane >> 2, c = lane & 3;
  const int bm = blockIdx.y * BM;

  const int half = blockIdx.x >> 1;  // 0 = E, 1 = A
  const int sub = blockIdx.x & 1;    // which 128-col slab
  const float* W = half ? Wa : We;
  const float* bias = half ? ba : be;
  float* outp = half ? g_A : g_E;
  const int nrow0 = sub * 128;

  for (int i = tid; i < BM; i += 256) rowA[i] = idx[bm + i];
  __syncthreads();

  float acc[MT][NT][4];
#pragma unroll
  for (int i = 0; i < MT; i++)
#pragma unroll
    for (int j = 0; j < NT; j++)
#pragma unroll
      for (int q = 0; q < 4; q++) acc[i][j][q] = 0.f;

  float4 ra[2], rb[2];
  const int fi0 = tid >> 2, kq0 = tid & 3;
  const int fi1 = (tid + 256) >> 2, kq1 = (tid + 256) & 3;

  auto loadT = [&](int kt, float4* a4, float4* b4) {
    int k0 = kt * BK;
    a4[0] = *(const float4*)(tab + (size_t)rowA[fi0] * K + k0 + kq0 * 4);
    a4[1] = *(const float4*)(tab + (size_t)rowA[fi1] * K + k0 + kq1 * 4);
    b4[0] = *(const float4*)(W + (size_t)(nrow0 + fi0) * K + k0 + kq0 * 4);
    b4[1] = *(const float4*)(W + (size_t)(nrow0 + fi1) * K + k0 + kq1 * 4);
  };
  auto storeT = [&](const float4* a4, const float4* b4) {
#pragma unroll
    for (int v = 0; v < 2; v++) {
      int i = v ? fi1 : fi0;
      int kb = (v ? kq1 : kq0) * 4;
      float4 x = a4[v];
      As[i][tpos(kb + 0)] = cvt_tf32(x.x);
      As[i][tpos(kb + 1)] = cvt_tf32(x.y);
      As[i][tpos(kb + 2)] = cvt_tf32(x.z);
      As[i][tpos(kb + 3)] = cvt_tf32(x.w);
      float4 y = b4[v];
      Bs[i][tpos(kb + 0)] = cvt_tf32(y.x);
      Bs[i][tpos(kb + 1)] = cvt_tf32(y.y);
      Bs[i][tpos(kb + 2)] = cvt_tf32(y.z);
      Bs[i][tpos(kb + 3)] = cvt_tf32(y.w);
    }
  };

  loadT(0, ra, rb);
  storeT(ra, rb);
  __syncthreads();

  for (int kt = 0; kt < KT; kt++) {
    float4 na[2], nb[2];
    if (kt + 1 < KT) loadT(kt + 1, na, nb);
#pragma unroll
    for (int kc = 0; kc < 2; kc++) {
      unsigned af[MT][4], bf[NT][2];
#pragma unroll
      for (int mt = 0; mt < MT; mt++) {
        int m = wm * 64 + mt * 16 + r;
        uint2 lo = *(const uint2*)&As[m][kc * 8 + 2 * c];
        uint2 hi = *(const uint2*)&As[m + 8][kc * 8 + 2 * c];
        af[mt][0] = lo.x; af[mt][2] = lo.y;
        af[mt][1] = hi.x; af[mt][3] = hi.y;
      }
#pragma unroll
      for (int nt = 0; nt < NT; nt++) {
        int n = wn * 32 + nt * 8 + r;
        uint2 bb = *(const uint2*)&Bs[n][kc * 8 + 2 * c];
        bf[nt][0] = bb.x; bf[nt][1] = bb.y;
      }
#pragma unroll
      for (int mt = 0; mt < MT; mt++)
#pragma unroll
        for (int nt = 0; nt < NT; nt++) mma_tf32(acc[mt][nt], af[mt], bf[nt]);
    }
    if (kt + 1 < KT) {
      __syncthreads();
      storeT(na, nb);
      __syncthreads();
    }
  }

  // epilogue: activation + store
#pragma unroll
  for (int mt = 0; mt < MT; mt++) {
#pragma unroll
    for (int nt = 0; nt < NT; nt++) {
      int rowL = wm * 64 + mt * 16 + r;
      int colL = wn * 32 + nt * 8 + 2 * c;
      int ncol = nrow0 + colL;
      float b0 = bias[ncol], b1 = bias[ncol + 1];
      float t0 = acc[mt][nt][0] + b0, t1 = acc[mt][nt][1] + b1;
      float t2 = acc[mt][nt][2] + b0, t3 = acc[mt][nt][3] + b1;
      if (half == 0) {
        t0 = 1.f / (1.f + expf(-t0)); t1 = 1.f / (1.f + expf(-t1));
        t2 = 1.f / (1.f + expf(-t2)); t3 = 1.f / (1.f + expf(-t3));
      } else {
        t0 = tanhf(t0); t1 = tanhf(t1); t2 = tanhf(t2); t3 = tanhf(t3);
      }
      float* o0 = outp + (size_t)(bm + rowL) * DV_ + ncol;
      float* o1 = outp + (size_t)(bm + rowL + 8) * DV_ + ncol;
      *(float2*)o0 = make_float2(t0, t1);
      *(float2*)o1 = make_float2(t2, t3);
    }
  }
}

// ================= fp32 gather GEMM (logits only: N=50, K=128) ======
template <int BM, int BN, int BK, int TM, int TN>
__global__ void __launch_bounds__((BM / TM) * (BN / TN)) sgemm_gather(
    const float* __restrict__ tab, const int* __restrict__ idx,
    const float* __restrict__ Wm, float* __restrict__ out, int ldOut, int N, int K) {
  constexpr int THREADS = (BM / TM) * (BN / TN);
  constexpr int TX = BN / TN;
  constexpr int AV = (BM * BK) / (4 * THREADS);
  constexpr int BV = (BN * BK) / (4 * THREADS);

  __shared__ float As[BK][BM];
  __shared__ float Bs[BK][BN];
  __shared__ int rowIdx[BM];

  const int tid = threadIdx.x;
  const int bm = blockIdx.y * BM;
  const int bn = blockIdx.x * BN;

  for (int i = tid; i < BM; i += THREADS) rowIdx[i] = idx[bm + i];
  __syncthreads();

  float acc[TM][TN];
#pragma unroll
  for (int i = 0; i < TM; i++)
#pragma unroll
    for (int j = 0; j < TN; j++) acc[i][j] = 0.f;

  const int tx = tid % TX;
  const int ty = tid / TX;

  for (int k0 = 0; k0 < K; k0 += BK) {
#pragma unroll
    for (int v = 0; v < AV; v++) {
      int f = tid + v * THREADS;
      int i = f / (BK / 4);
      int kv = f % (BK / 4);
      float4 a4 = *(const float4*)(tab + (size_t)rowIdx[i] * K + k0 + kv * 4);
      As[kv * 4 + 0][i] = a4.x; As[kv * 4 + 1][i] = a4.y;
      As[kv * 4 + 2][i] = a4.z; As[kv * 4 + 3][i] = a4.w;
    }
#pragma unroll
    for (int v = 0; v < BV; v++) {
      int f = tid + v * THREADS;
      int n = f / (BK / 4);
      int kv = f % (BK / 4);
      float4 b4 = make_float4(0.f, 0.f, 0.f, 0.f);
      if (bn + n < N) b4 = *(const float4*)(Wm + (size_t)(bn + n) * K + k0 + kv * 4);
      Bs[kv * 4 + 0][n] = b4.x; Bs[kv * 4 + 1][n] = b4.y;
      Bs[kv * 4 + 2][n] = b4.z; Bs[kv * 4 + 3][n] = b4.w;
    }
    __syncthreads();
#pragma unroll
    for (int kk = 0; kk < BK; kk++) {
      float ar[TM], br[TN];
#pragma unroll
      for (int i4 = 0; i4 < TM; i4 += 4) {
        float4 t4 = *(const float4*)(&As[kk][ty * TM + i4]);
        ar[i4 + 0] = t4.x; ar[i4 + 1] = t4.y; ar[i4 + 2] = t4.z; ar[i4 + 3] = t4.w;
      }
#pragma unroll
      for (int j4 = 0; j4 < TN; j4 += 4) {
        float4 t4 = *(const float4*)(&Bs[kk][tx * TN + j4]);
        br[j4 + 0] = t4.x; br[j4 + 1] = t4.y; br[j4 + 2] = t4.z; br[j4 + 3] = t4.w;
      }
#pragma unroll
      for (int i = 0; i < TM; i++)
#pragma unroll
        for (int j = 0; j < TN; j++) acc[i][j] = fmaf(ar[i], br[j], acc[i][j]);
    }
    __syncthreads();
  }

#pragma unroll
  for (int i = 0; i < TM; i++) {
    size_t rrow = (size_t)(bm + ty * TM + i);
#pragma unroll
    for (int j = 0; j < TN; j++) {
      int n = bn + tx * TN + j;
      if (n < N) out[rrow * ldOut + n] = acc[i][j];
    }
  }
}

// ---------------- softmax over M_=50 per row ----------------
__global__ void __launch_bounds__(256) softmax_kernel() {
  int gw = (blockIdx.x * blockDim.x + threadIdx.x) >> 5;
  if (gw >= BT_) return;
  int lane = threadIdx.x & 31;
  float* w = g_Wt + (size_t)gw * M_;
  float v0 = w[lane];
  float v1 = (lane + 32 < M_) ? w[lane + 32] : -1e30f;
  float mx = fmaxf(v0, v1);
#pragma unroll
  for (int o = 16; o; o >>= 1) mx = fmaxf(mx, __shfl_xor_sync(0xffffffffu, mx, o));
  float e0 = expf(v0 - mx);
  float e1 = (lane + 32 < M_) ? expf(v1 - mx) : 0.f;
  float s = e0 + e1;
#pragma unroll
  for (int o = 16; o; o >>= 1) s += __shfl_xor_sync(0xffffffffu, s, o);
  float inv = 1.f / s;
  w[lane] = e0 * inv;
  if (lane + 32 < M_) w[lane + 32] = e1 * inv;
}

// ---------------- gather q_e into FEAT[:, 256:384] ----------------
__global__ void __launch_bounds__(256) gatherq_kernel(
    const float* __restrict__ q_tab, const int* __restrict__ q_data) {
  int gid = blockIdx.x * blockDim.x + threadIdx.x;
  int row = gid >> 5;
  int c = (gid & 31) << 2;
  float4 v = *(const float4*)(q_tab + (size_t)q_data[row] * DK_ + c);
  *(float4*)(g_FEAT + (size_t)row * KF_ + DV_ + c) = v;
}

// ---------------- scan: one CTA per batch element, f32x2 packed ----------------
__global__ void __launch_bounds__(256) scan_kernel(
    const float* __restrict__ Mv0, const int* __restrict__ q_data) {
  const int b = blockIdx.x;
  const int d = threadIdx.x;
  __shared__ __align__(8) float ws[2][52];

  unsigned long long mv[M_ / 2];
#pragma unroll
  for (int i = 0; i < M_ / 2; i++)
    mv[i] = pack2(Mv0[(2 * i) * DV_ + d], Mv0[(2 * i + 1) * DV_ + d]);

  const size_t row0 = (size_t)b * T_;
  float e = g_E[row0 * DV_ + d];
  float a = g_A[row0 * DV_ + d];
  int qi = q_data[row0];
  if (d < M_) ws[0][d] = g_Wt[row0 * M_ + d];
  __syncthreads();

  int cur = 0;
  for (int t = 0; t < T_; t++) {
    size_t row = row0 + t;
    float e2 = 0.f, a2 = 0.f, w2 = 0.f;
    int qi2 = 0;
    if (t + 1 < T_) {
      size_t rn = row + 1;
      e2 = g_E[rn * DV_ + d];
      a2 = g_A[rn * DV_ + d];
      if (d < M_) w2 = g_Wt[rn * M_ + d];
      qi2 = q_data[rn];
    }

    unsigned long long rd0 = 0ULL, rd1 = 0ULL;
    if (qi >= 1) {
      unsigned long long ne2 = pack2(-e, -e);
      unsigned long long ad2 = pack2(a, a);
#pragma unroll
      for (int i = 0; i < M_ / 2; i++) {
        unsigned long long wp = *(const unsigned long long*)&ws[cur][2 * i];
        if (i & 1) rd1 = fma2(wp, mv[i], rd1); else rd0 = fma2(wp, mv[i], rd0);
        unsigned long long tt = fma2(mv[i], ne2, ad2);  // a - mv*e
        mv[i] = fma2(wp, tt, mv[i]);                    // mv + w*(a - mv*e)
      }
    } else {
#pragma unroll
      for (int i = 0; i < M_ / 2; i++) {
        unsigned long long wp = *(const unsigned long long*)&ws[cur][2 * i];
        if (i & 1) rd1 = fma2(wp, mv[i], rd1); else rd0 = fma2(wp, mv[i], rd0);
      }
    }
    float2 s0 = unpack2(rd0), s1 = unpack2(rd1);
    g_FEAT[row * KF_ + d] = (s0.x + s0.y) + (s1.x + s1.y);

    if (d < M_) ws[cur ^ 1][d] = w2;
    __syncthreads();
    e = e2; a = a2; qi = qi2; cur ^= 1;
  }
}

// ================= final tf32 GEMM + fused head =================
// h = tanh(FEAT @ Wr^T + br); pred = h@Wp + bp; probs; masked BCE partials
__global__ void __launch_bounds__(256) final_tf32(
    const float* __restrict__ Wr, const float* __restrict__ br,
    const float* __restrict__ Wp, const float* __restrict__ bp,
    const float* __restrict__ target, float* __restrict__ out_probs) {
  constexpr int BM = 128, BK = 16, K = KF_, KT = K / BK;
  constexpr int MT = 2, NT = 8;  // warp tile 32x64, warp grid 4x2

  __shared__ unsigned As[BM][18];
  __shared__ unsigned Bs[128][18];
  __shared__ float sBr[128], sWp[128];
  __shared__ float red[128][2];
  __shared__ float sl[128], sv[128];

  const int tid = threadIdx.x;
  const int wid = tid >> 5, lane = tid & 31;
  const int wm = wid >> 1, wn = wid & 1;  // 4 x 2
  const int r = lane >> 2, c = lane & 3;
  const int bm = blockIdx.y * BM;

  if (tid < 128) { sBr[tid] = br[tid]; sWp[tid] = Wp[tid]; }

  float acc[MT][NT][4];
#pragma unroll
  for (int i = 0; i < MT; i++)
#pragma unroll
    for (int j = 0; j < NT; j++)
#pragma unroll
      for (int q = 0; q < 4; q++) acc[i][j][q] = 0.f;

  const int fi0 = tid >> 2, kq0 = tid & 3;
  const int fi1 = (tid + 256) >> 2, kq1 = (tid + 256) & 3;

  auto loadT = [&](int kt, float4* a4, float4* b4) {
    int k0 = kt * BK;
    a4[0] = *(const float4*)(g_FEAT + (size_t)(bm + fi0) * K + k0 + kq0 * 4);
    a4[1] = *(const float4*)(g_FEAT + (size_t)(bm + fi1) * K + k0 + kq1 * 4);
    b4[0] = *(const float4*)(Wr + (size_t)fi0 * K + k0 + kq0 * 4);
    b4[1] = *(const float4*)(Wr + (size_t)fi1 * K + k0 + kq1 * 4);
  };
  auto storeT = [&](const float4* a4, const float4* b4) {
#pragma unroll
    for (int v = 0; v < 2; v++) {
      int i = v ? fi1 : fi0;
      int kb = (v ? kq1 : kq0) * 4;
      float4 x = a4[v];
      As[i][tpos(kb + 0)] = cvt_tf32(x.x);
      As[i][tpos(kb + 1)] = cvt_tf32(x.y);
      As[i][tpos(kb + 2)] = cvt_tf32(x.z);
      As[i][tpos(kb + 3)] = cvt_tf32(x.w);
      float4 y = b4[v];
      Bs[i][tpos(kb + 0)] = cvt_tf32(y.x);
      Bs[i][tpos(kb + 1)] = cvt_tf32(y.y);
      Bs[i][tpos(kb + 2)] = cvt_tf32(y.z);
      Bs[i][tpos(kb + 3)] = cvt_tf32(y.w);
    }
  };

  float4 ra[2], rb[2];
  loadT(0, ra, rb);
  storeT(ra, rb);
  __syncthreads();

  for (int kt = 0; kt < KT; kt++) {
    float4 na[2], nb[2];
    if (kt + 1 < KT) loadT(kt + 1, na, nb);
#pragma unroll
    for (int kc = 0; kc < 2; kc++) {
      unsigned af[MT][4], bf[NT][2];
#pragma unroll
      for (int mt = 0; mt < MT; mt++) {
        int m = wm * 32 + mt * 16 + r;
        uint2 lo = *(const uint2*)&As[m][kc * 8 + 2 * c];
        uint2 hi = *(const uint2*)&As[m + 8][kc * 8 + 2 * c];
        af[mt][0] = lo.x; af[mt][2] = lo.y;
        af[mt][1] = hi.x; af[mt][3] = hi.y;
      }
#pragma unroll
      for (int nt = 0; nt < NT; nt++) {
        int n = wn * 64 + nt * 8 + r;
        uint2 bb = *(const uint2*)&Bs[n][kc * 8 + 2 * c];
        bf[nt][0] = bb.x; bf[nt][1] = bb.y;
      }
#pragma unroll
      for (int mt = 0; mt < MT; mt++)
#pragma unroll
        for (int nt = 0; nt < NT; nt++) mma_tf32(acc[mt][nt], af[mt], bf[nt]);
    }
    if (kt + 1 < KT) {
      __syncthreads();
      storeT(na, nb);
      __syncthreads();
    }
  }
  __syncthreads();  // sBr/sWp ready (and smem reads done)

  // partial pred sums per owned row
  float ps[4] = {0.f, 0.f, 0.f, 0.f};
#pragma unroll
  for (int nt = 0; nt < NT; nt++) {
#pragma unroll
    for (int j = 0; j < 2; j++) {
      int n = wn * 64 + nt * 8 + 2 * c + j;
      float bb = sBr[n], wp = sWp[n];
#pragma unroll
      for (int mt = 0; mt < MT; mt++) {
        float h0 = tanhf(acc[mt][nt][j] + bb);      // row r
        float h1 = tanhf(acc[mt][nt][2 + j] + bb);  // row r+8
        ps[mt * 2 + 0] = fmaf(h0, wp, ps[mt * 2 + 0]);
        ps[mt * 2 + 1] = fmaf(h1, wp, ps[mt * 2 + 1]);
      }
    }
  }
#pragma unroll
  for (int off = 1; off <= 2; off <<= 1)
#pragma unroll
    for (int i = 0; i < 4; i++) ps[i] += __shfl_xor_sync(0xffffffffu, ps[i], off);
  if (c == 0) {
#pragma unroll
    for (int mt = 0; mt < MT; mt++)
#pragma unroll
      for (int hf = 0; hf < 2; hf++)
        red[wm * 32 + mt * 16 + r + hf * 8][wn] = ps[mt * 2 + hf];
  }
  __syncthreads();

  float per = 0.f, val = 0.f;
  if (tid < 128) {
    float p = bp[0] + red[tid][0] + red[tid][1];
    size_t row = (size_t)bm + tid;
    out_probs[row] = 1.f / (1.f + expf(-p));
    float tg = target[row];
    if (tg >= 0.f) {
      per = fmaxf(p, 0.f) - p * tg + log1pf(expf(-fabsf(p)));
      val = 1.f;
    }
  }
  __syncthreads();
  if (tid < 128) { sl[tid] = per; sv[tid] = val; }
  __syncthreads();
  for (int s = 64; s > 0; s >>= 1) {
    if (tid < s) { sl[tid] += sl[tid + s]; sv[tid] += sv[tid + s]; }
    __syncthreads();
  }
  if (tid == 0) {
    g_part[2 * blockIdx.y] = sl[0];
    g_part[2 * blockIdx.y + 1] = sv[0];
  }
}

// ---------------- final loss reduction ----------------
__global__ void __launch_bounds__(256) finalize_kernel(float* __restrict__ out) {
  __shared__ float sl[256], sv[256];
  int tid = threadIdx.x;
  float l = 0.f, v = 0.f;
  for (int i = tid; i < BT_ / 128; i += 256) {
    l += g_part[2 * i];
    v += g_part[2 * i + 1];
  }
  sl[tid] = l; sv[tid] = v;
  __syncthreads();
  for (int s = 128; s > 0; s >>= 1) {
    if (tid < s) { sl[tid] += sl[tid + s]; sv[tid] += sv[tid + s]; }
    __syncthreads();
  }
  if (tid == 0) out[0] = sl[0] / fmaxf(sv[0], 1.f);
}

// ---------------- launch ----------------
extern "C" void kernel_launch(void* const* d_in, const int* in_sizes, int n_in,
                              void* d_out, int out_size) {
  const int* q_data = (const int*)d_in[0];
  const int* qa_data = (const int*)d_in[1];
  const float* target = (const float*)d_in[2];
  const float* q_tab = (const float*)d_in[3];
  const float* qa_tab = (const float*)d_in[4];
  const float* Mk = (const float*)d_in[5];
  const float* Mv0 = (const float*)d_in[6];
  const float* We = (const float*)d_in[7];
  const float* be = (const float*)d_in[8];
  const float* Wa = (const float*)d_in[9];
  const float* ba = (const float*)d_in[10];
  const float* Wr = (const float*)d_in[11];
  const float* br = (const float*)d_in[12];
  const float* Wp = (const float*)d_in[13];
  const float* bp = (const float*)d_in[14];
  float* out = (float*)d_out;

  float* pW; cudaGetSymbolAddress((void**)&pW, g_Wt);

  gemm_ea_tf32<<<dim3(4, BT_ / 128), 256>>>(qa_tab, qa_data, We, be, Wa, ba);
  sgemm_gather<128, 64, 16, 8, 4><<<dim3(1, BT_ / 128), 256>>>(
      q_tab, q_data, Mk, pW, M_, M_, DK_);
  softmax_kernel<<<BT_ / 8, 256>>>();
  gatherq_kernel<<<BT_ / 8, 256>>>(q_tab, q_data);
  scan_kernel<<<B_, 256>>>(Mv0, q_data);
  final_tf32<<<dim3(1, BT_ / 128), 256>>>(Wr, br, Wp, bp, target, out + 1);
  finalize_kernel<<<1, 256>>>(out);
}

// round 3
// speedup vs baseline: 2.5082x; 1.4153x over previous
#include <cuda_runtime.h>
#include <cuda_bf16.h>
#include <math.h>

#define B_  256
#define T_  500
#define BT_ 128000
#define DK_ 128
#define DV_ 256
#define M_  50
#define LW_ 52    // padded row stride of softmax weights (16B-aligned rows)
#define KF_ 384   // DV + DK

// ---------------- scratch ----------------
__device__ float g_E[(size_t)BT_ * DV_];
__device__ float g_A[(size_t)BT_ * DV_];
__device__ float g_Wt[(size_t)BT_ * LW_];
__device__ float g_READ[(size_t)BT_ * DV_];
__device__ float g_part[2 * (BT_ / 128)];

// ---------------- helpers ----------------
__device__ __forceinline__ unsigned cvt_tf32(float x) {
  unsigned u;
  asm("cvt.rna.tf32.f32 %0, %1;" : "=r"(u) : "f"(x));
  return u;
}
__device__ __forceinline__ unsigned pack_bf16(float lo, float hi) {
  unsigned r;
  asm("cvt.rn.bf16x2.f32 %0, %1, %2;" : "=r"(r) : "f"(hi), "f"(lo));
  return r;
}
__device__ __forceinline__ void mma_tf32(float* c, const unsigned* a, const unsigned* b) {
  asm volatile(
      "mma.sync.aligned.m16n8k8.row.col.f32.tf32.tf32.f32 "
      "{%0,%1,%2,%3}, {%4,%5,%6,%7}, {%8,%9}, {%0,%1,%2,%3};\n"
      : "+f"(c[0]), "+f"(c[1]), "+f"(c[2]), "+f"(c[3])
      : "r"(a[0]), "r"(a[1]), "r"(a[2]), "r"(a[3]), "r"(b[0]), "r"(b[1]));
}
__device__ __forceinline__ void mma_bf16(float* c, const unsigned* a, const unsigned* b) {
  asm volatile(
      "mma.sync.aligned.m16n8k16.row.col.f32.bf16.bf16.f32 "
      "{%0,%1,%2,%3}, {%4,%5,%6,%7}, {%8,%9}, {%0,%1,%2,%3};\n"
      : "+f"(c[0]), "+f"(c[1]), "+f"(c[2]), "+f"(c[3])
      : "r"(a[0]), "r"(a[1]), "r"(a[2]), "r"(a[3]), "r"(b[0]), "r"(b[1]));
}
// pair-position permutation within one 16-wide k-chunk (8 bf16x2 pairs):
// pair j (values 2j,2j+1) -> slot 2*(j&3) + (j>>2), so a thread's uint2 at
// slot 2c holds pairs {c, c+4} = k {2c,2c+1} and {2c+8,2c+9}.
__host__ __device__ __forceinline__ constexpr int ppos(int j) {
  return 2 * (j & 3) + (j >> 2);
}
// 32-bit tf32 permutation (value granularity, per 8-wide chunk)
__host__ __device__ __forceinline__ constexpr int tpos(int kl) {
  return (kl >> 3) * 8 + 2 * (kl & 3) + ((kl & 7) >> 2);
}

__device__ __forceinline__ unsigned long long pack2(float lo, float hi) {
  unsigned long long r;
  asm("mov.b64 %0, {%1,%2};" : "=l"(r) : "f"(lo), "f"(hi));
  return r;
}
__device__ __forceinline__ unsigned long long fma2(unsigned long long a,
                                                   unsigned long long b,
                                                   unsigned long long c) {
  unsigned long long d;
  asm("fma.rn.f32x2 %0, %1, %2, %3;" : "=l"(d) : "l"(a), "l"(b), "l"(c));
  return d;
}
__device__ __forceinline__ float2 unpack2(unsigned long long v) {
  float2 f;
  asm("mov.b64 {%0,%1}, %2;" : "=f"(f.x), "=f"(f.y) : "l"(v));
  return f;
}

// ================= bf16 GEMM: E and A fused (grid.x: 0,1 -> E; 2,3 -> A) =====
__global__ void __launch_bounds__(256) gemm_ea_bf16(
    const float* __restrict__ tab, const int* __restrict__ idx,
    const float* __restrict__ We, const float* __restrict__ be,
    const float* __restrict__ Wa, const float* __restrict__ ba) {
  constexpr int BM = 128, BK = 16, K = 256, KT = K / BK;
  constexpr int MT = 4, NT = 4;  // warp tile 64x32, warp grid 2x4

  __shared__ unsigned As[BM][10];
  __shared__ unsigned Bs[128][10];
  __shared__ int rowA[BM];

  const int tid = threadIdx.x;
  const int wid = tid >> 5, lane = tid & 31;
  const int wm = wid >> 2, wn = wid & 3;
  const int r = lane >> 2, c = lane & 3;
  const int bm = blockIdx.y * BM;

  const int half = blockIdx.x >> 1;
  const int sub = blockIdx.x & 1;
  const float* W = half ? Wa : We;
  const float* bias = half ? ba : be;
  float* outp = half ? g_A : g_E;
  const int nrow0 = sub * 128;

  for (int i = tid; i < BM; i += 256) rowA[i] = idx[bm + i];
  __syncthreads();

  float acc[MT][NT][4];
#pragma unroll
  for (int i = 0; i < MT; i++)
#pragma unroll
    for (int j = 0; j < NT; j++)
#pragma unroll
      for (int q = 0; q < 4; q++) acc[i][j][q] = 0.f;

  const int fi0 = tid >> 2, kq0 = tid & 3;

  auto loadT = [&](int kt, float4* a4, float4* b4) {
    int k0 = kt * BK;
    a4[0] = *(const float4*)(tab + (size_t)rowA[fi0] * K + k0 + kq0 * 4);
    a4[1] = *(const float4*)(tab + (size_t)rowA[fi0 + 64] * K + k0 + kq0 * 4);
    b4[0] = *(const float4*)(W + (size_t)(nrow0 + fi0) * K + k0 + kq0 * 4);
    b4[1] = *(const float4*)(W + (size_t)(nrow0 + fi0 + 64) * K + k0 + kq0 * 4);
  };
  auto storeT = [&](const float4* a4, const float4* b4) {
#pragma unroll
    for (int v = 0; v < 2; v++) {
      int i = fi0 + v * 64;
      float4 x = a4[v];
      As[i][ppos(2 * kq0)] = pack_bf16(x.x, x.y);
      As[i][ppos(2 * kq0 + 1)] = pack_bf16(x.z, x.w);
      float4 y = b4[v];
      Bs[i][ppos(2 * kq0)] = pack_bf16(y.x, y.y);
      Bs[i][ppos(2 * kq0 + 1)] = pack_bf16(y.z, y.w);
    }
  };

  float4 ra[2], rb[2];
  loadT(0, ra, rb);
  storeT(ra, rb);
  __syncthreads();

  for (int kt = 0; kt < KT; kt++) {
    float4 na[2], nb[2];
    if (kt + 1 < KT) loadT(kt + 1, na, nb);
    unsigned af[MT][4], bf[NT][2];
#pragma unroll
    for (int mt = 0; mt < MT; mt++) {
      int m = wm * 64 + mt * 16 + r;
      uint2 lo = *(const uint2*)&As[m][2 * c];
      uint2 hi = *(const uint2*)&As[m + 8][2 * c];
      af[mt][0] = lo.x; af[mt][2] = lo.y;
      af[mt][1] = hi.x; af[mt][3] = hi.y;
    }
#pragma unroll
    for (int nt = 0; nt < NT; nt++) {
      int n = wn * 32 + nt * 8 + r;
      uint2 bb = *(const uint2*)&Bs[n][2 * c];
      bf[nt][0] = bb.x; bf[nt][1] = bb.y;
    }
#pragma unroll
    for (int mt = 0; mt < MT; mt++)
#pragma unroll
      for (int nt = 0; nt < NT; nt++) mma_bf16(acc[mt][nt], af[mt], bf[nt]);
    if (kt + 1 < KT) {
      __syncthreads();
      storeT(na, nb);
      __syncthreads();
    }
  }

#pragma unroll
  for (int mt = 0; mt < MT; mt++) {
#pragma unroll
    for (int nt = 0; nt < NT; nt++) {
      int rowL = wm * 64 + mt * 16 + r;
      int ncol = nrow0 + wn * 32 + nt * 8 + 2 * c;
      float b0 = bias[ncol], b1 = bias[ncol + 1];
      float t0 = acc[mt][nt][0] + b0, t1 = acc[mt][nt][1] + b1;
      float t2 = acc[mt][nt][2] + b0, t3 = acc[mt][nt][3] + b1;
      if (half == 0) {
        t0 = 1.f / (1.f + expf(-t0)); t1 = 1.f / (1.f + expf(-t1));
        t2 = 1.f / (1.f + expf(-t2)); t3 = 1.f / (1.f + expf(-t3));
      } else {
        t0 = tanhf(t0); t1 = tanhf(t1); t2 = tanhf(t2); t3 = tanhf(t3);
      }
      *(float2*)(outp + (size_t)(bm + rowL) * DV_ + ncol) = make_float2(t0, t1);
      *(float2*)(outp + (size_t)(bm + rowL + 8) * DV_ + ncol) = make_float2(t2, t3);
    }
  }
}

// ================= bf16 logits GEMM + fused softmax =================
// w[row] = softmax( gather(q_tab, q_data) @ Mk^T ), rows of 50, stored stride 52
__global__ void __launch_bounds__(256) logits_softmax_bf16(
    const float* __restrict__ q_tab, const int* __restrict__ q_data,
    const float* __restrict__ Mk) {
  constexpr int BM = 128, BK = 16, K = 128, KT = K / BK;
  constexpr int MT = 2, NT = 4;  // warp tile 32x32, warp grid 4x2

  __shared__ unsigned As[BM][10];
  __shared__ unsigned Bs[64][10];
  __shared__ int rowA[BM];
  __shared__ float sLg[BM][65];
  __shared__ float sInv[BM];

  const int tid = threadIdx.x;
  const int wid = tid >> 5, lane = tid & 31;
  const int wm = wid >> 1, wn = wid & 1;
  const int r = lane >> 2, c = lane & 3;
  const int bm = blockIdx.x * BM;

  for (int i = tid; i < BM; i += 256) rowA[i] = q_data[bm + i];
  __syncthreads();

  float acc[MT][NT][4];
#pragma unroll
  for (int i = 0; i < MT; i++)
#pragma unroll
    for (int j = 0; j < NT; j++)
#pragma unroll
      for (int q = 0; q < 4; q++) acc[i][j][q] = 0.f;

  const int fi0 = tid >> 2, kq0 = tid & 3;
  const bool bAct = fi0 < 50;  // B rows beyond 50 are zero

  auto loadT = [&](int kt, float4* a4, float4* b4) {
    int k0 = kt * BK;
    a4[0] = *(const float4*)(q_tab + (size_t)rowA[fi0] * K + k0 + kq0 * 4);
    a4[1] = *(const float4*)(q_tab + (size_t)rowA[fi0 + 64] * K + k0 + kq0 * 4);
    b4[0] = bAct ? *(const float4*)(Mk + (size_t)fi0 * K + k0 + kq0 * 4)
                 : make_float4(0.f, 0.f, 0.f, 0.f);
  };
  auto storeT = [&](const float4* a4, const float4* b4) {
#pragma unroll
    for (int v = 0; v < 2; v++) {
      int i = fi0 + v * 64;
      float4 x = a4[v];
      As[i][ppos(2 * kq0)] = pack_bf16(x.x, x.y);
      As[i][ppos(2 * kq0 + 1)] = pack_bf16(x.z, x.w);
    }
    float4 y = b4[0];
    Bs[fi0][ppos(2 * kq0)] = pack_bf16(y.x, y.y);
    Bs[fi0][ppos(2 * kq0 + 1)] = pack_bf16(y.z, y.w);
  };

  float4 ra[2], rb[1];
  loadT(0, ra, rb);
  storeT(ra, rb);
  __syncthreads();

  for (int kt = 0; kt < KT; kt++) {
    float4 na[2], nb[1];
    if (kt + 1 < KT) loadT(kt + 1, na, nb);
    unsigned af[MT][4], bf[NT][2];
#pragma unroll
    for (int mt = 0; mt < MT; mt++) {
      int m = wm * 32 + mt * 16 + r;
      uint2 lo = *(const uint2*)&As[m][2 * c];
      uint2 hi = *(const uint2*)&As[m + 8][2 * c];
      af[mt][0] = lo.x; af[mt][2] = lo.y;
      af[mt][1] = hi.x; af[mt][3] = hi.y;
    }
#pragma unroll
    for (int nt = 0; nt < NT; nt++) {
      int n = wn * 32 + nt * 8 + r;
      uint2 bb = *(const uint2*)&Bs[n][2 * c];
      bf[nt][0] = bb.x; bf[nt][1] = bb.y;
    }
#pragma unroll
    for (int mt = 0; mt < MT; mt++)
#pragma unroll
      for (int nt = 0; nt < NT; nt++) mma_bf16(acc[mt][nt], af[mt], bf[nt]);
    if (kt + 1 < KT) {
      __syncthreads();
      storeT(na, nb);
      __syncthreads();
    }
  }

  // dump logits to smem
#pragma unroll
  for (int mt = 0; mt < MT; mt++) {
#pragma unroll
    for (int nt = 0; nt < NT; nt++) {
      int rowL = wm * 32 + mt * 16 + r;
      int colL = wn * 32 + nt * 8 + 2 * c;
      sLg[rowL][colL] = acc[mt][nt][0];
      sLg[rowL][colL + 1] = acc[mt][nt][1];
      sLg[rowL + 8][colL] = acc[mt][nt][2];
      sLg[rowL + 8][colL + 1] = acc[mt][nt][3];
    }
  }
  __syncthreads();

  // softmax per row (threads 0..127, one row each)
  if (tid < BM) {
    float mx = -1e30f;
#pragma unroll 10
    for (int j = 0; j < M_; j++) mx = fmaxf(mx, sLg[tid][j]);
    float s = 0.f;
#pragma unroll 10
    for (int j = 0; j < M_; j++) {
      float ev = expf(sLg[tid][j] - mx);
      sLg[tid][j] = ev;
      s += ev;
    }
    sInv[tid] = 1.f / s;
  }
  __syncthreads();

  // coalesced write, stride LW_ with zero pad cols 50..51
  for (int f = tid; f < BM * LW_; f += 256) {
    int rowL = f / LW_;
    int j = f - rowL * LW_;
    float v = (j < M_) ? sLg[rowL][j] * sInv[rowL] : 0.f;
    g_Wt[(size_t)(bm + rowL) * LW_ + j] = v;
  }
}

// ---------------- scan: one CTA per batch element, barrier-free ----------------
__global__ void __launch_bounds__(256) scan_kernel(
    const float* __restrict__ Mv0, const int* __restrict__ q_data) {
  const int b = blockIdx.x;
  const int d = threadIdx.x;
  const int wid = d >> 5, lane = d & 31;
  __shared__ __align__(16) float ws_all[8][64];  // per-warp w copy
  float* ws = ws_all[wid];

  unsigned long long mv[M_ / 2];
#pragma unroll
  for (int i = 0; i < M_ / 2; i++)
    mv[i] = pack2(Mv0[(2 * i) * DV_ + d], Mv0[(2 * i + 1) * DV_ + d]);

  const size_t row0 = (size_t)b * T_;
  float e = g_E[row0 * DV_ + d];
  float a = g_A[row0 * DV_ + d];
  int qi = q_data[row0];
  if (lane < 13)
    *(float4*)&ws[lane * 4] = *(const float4*)(g_Wt + row0 * LW_ + lane * 4);
  // same warp produces & consumes ws: program order suffices, no barrier.

  for (int t = 0; t < T_; t++) {
    const size_t row = row0 + t;
    const size_t rn = row0 + (t + 1 < T_ ? t + 1 : t);
    // prefetch next step
    float e2 = g_E[rn * DV_ + d];
    float a2 = g_A[rn * DV_ + d];
    int qi2 = q_data[rn];
    float4 wv;
    if (lane < 13) wv = *(const float4*)(g_Wt + rn * LW_ + lane * 4);

    unsigned long long rd0 = 0ULL, rd1 = 0ULL;
    if (qi >= 1) {
      unsigned long long ne2 = pack2(-e, -e);
      unsigned long long ad2 = pack2(a, a);
#pragma unroll
      for (int j = 0; j < 12; j++) {
        ulonglong2 wp = *(const ulonglong2*)&ws[4 * j];
        rd0 = fma2(wp.x, mv[2 * j], rd0);
        unsigned long long t0 = fma2(mv[2 * j], ne2, ad2);
        mv[2 * j] = fma2(wp.x, t0, mv[2 * j]);
        rd1 = fma2(wp.y, mv[2 * j + 1], rd1);
        unsigned long long t1 = fma2(mv[2 * j + 1], ne2, ad2);
        mv[2 * j + 1] = fma2(wp.y, t1, mv[2 * j + 1]);
      }
      unsigned long long wl = *(const unsigned long long*)&ws[48];
      rd0 = fma2(wl, mv[24], rd0);
      unsigned long long tl = fma2(mv[24], ne2, ad2);
      mv[24] = fma2(wl, tl, mv[24]);
    } else {
#pragma unroll
      for (int j = 0; j < 12; j++) {
        ulonglong2 wp = *(const ulonglong2*)&ws[4 * j];
        rd0 = fma2(wp.x, mv[2 * j], rd0);
        rd1 = fma2(wp.y, mv[2 * j + 1], rd1);
      }
      unsigned long long wl = *(const unsigned long long*)&ws[48];
      rd0 = fma2(wl, mv[24], rd0);
    }
    float2 s0 = unpack2(rd0), s1 = unpack2(rd1);
    g_READ[row * DV_ + d] = (s0.x + s0.y) + (s1.x + s1.y);

    if (lane < 13) *(float4*)&ws[lane * 4] = wv;  // after all reads of ws
    e = e2; a = a2; qi = qi2;
  }
}

// ================= final tf32 GEMM (A gathers READ | q_e) + fused head =======
__global__ void __launch_bounds__(256) final_tf32(
    const float* __restrict__ q_tab, const int* __restrict__ q_data,
    const float* __restrict__ Wr, const float* __restrict__ br,
    const float* __restrict__ Wp, const float* __restrict__ bp,
    const float* __restrict__ target, float* __restrict__ out_probs) {
  constexpr int BM = 128, BK = 16, K = KF_, KT = K / BK;
  constexpr int MT = 2, NT = 8;  // warp tile 32x64, warp grid 4x2

  __shared__ unsigned As[BM][18];
  __shared__ unsigned Bs[128][18];
  __shared__ int rowA[BM];
  __shared__ float sBr[128], sWp[128];
  __shared__ float red[128][2];
  __shared__ float sl[128], sv[128];

  const int tid = threadIdx.x;
  const int wid = tid >> 5, lane = tid & 31;
  const int wm = wid >> 1, wn = wid & 1;
  const int r = lane >> 2, c = lane & 3;
  const int bm = blockIdx.y * BM;

  if (tid < 128) { sBr[tid] = br[tid]; sWp[tid] = Wp[tid]; }
  for (int i = tid; i < BM; i += 256) rowA[i] = q_data[bm + i];
  __syncthreads();

  float acc[MT][NT][4];
#pragma unroll
  for (int i = 0; i < MT; i++)
#pragma unroll
    for (int j = 0; j < NT; j++)
#pragma unroll
      for (int q = 0; q < 4; q++) acc[i][j][q] = 0.f;

  const int fi0 = tid >> 2, kq0 = tid & 3;

  auto loadA1 = [&](int fi, int kk) -> float4 {
    if (kk < DV_)
      return *(const float4*)(g_READ + (size_t)(bm + fi) * DV_ + kk);
    return *(const float4*)(q_tab + (size_t)rowA[fi] * DK_ + (kk - DV_));
  };
  auto loadT = [&](int kt, float4* a4, float4* b4) {
    int kk = kt * BK + kq0 * 4;
    a4[0] = loadA1(fi0, kk);
    a4[1] = loadA1(fi0 + 64, kk);
    b4[0] = *(const float4*)(Wr + (size_t)fi0 * K + kk);
    b4[1] = *(const float4*)(Wr + (size_t)(fi0 + 64) * K + kk);
  };
  auto storeT = [&](const float4* a4, const float4* b4) {
#pragma unroll
    for (int v = 0; v < 2; v++) {
      int i = fi0 + v * 64;
      int kb = kq0 * 4;
      float4 x = a4[v];
      As[i][tpos(kb + 0)] = cvt_tf32(x.x);
      As[i][tpos(kb + 1)] = cvt_tf32(x.y);
      As[i][tpos(kb + 2)] = cvt_tf32(x.z);
      As[i][tpos(kb + 3)] = cvt_tf32(x.w);
      float4 y = b4[v];
      Bs[i][tpos(kb + 0)] = cvt_tf32(y.x);
      Bs[i][tpos(kb + 1)] = cvt_tf32(y.y);
      Bs[i][tpos(kb + 2)] = cvt_tf32(y.z);
      Bs[i][tpos(kb + 3)] = cvt_tf32(y.w);
    }
  };

  float4 ra[2], rb[2];
  loadT(0, ra, rb);
  storeT(ra, rb);
  __syncthreads();

  for (int kt = 0; kt < KT; kt++) {
    float4 na[2], nb[2];
    if (kt + 1 < KT) loadT(kt + 1, na, nb);
#pragma unroll
    for (int kc = 0; kc < 2; kc++) {
      unsigned af[MT][4], bf[NT][2];
#pragma unroll
      for (int mt = 0; mt < MT; mt++) {
        int m = wm * 32 + mt * 16 + r;
        uint2 lo = *(const uint2*)&As[m][kc * 8 + 2 * c];
        uint2 hi = *(const uint2*)&As[m + 8][kc * 8 + 2 * c];
        af[mt][0] = lo.x; af[mt][2] = lo.y;
        af[mt][1] = hi.x; af[mt][3] = hi.y;
      }
#pragma unroll
      for (int nt = 0; nt < NT; nt++) {
        int n = wn * 64 + nt * 8 + r;
        uint2 bb = *(const uint2*)&Bs[n][kc * 8 + 2 * c];
        bf[nt][0] = bb.x; bf[nt][1] = bb.y;
      }
#pragma unroll
      for (int mt = 0; mt < MT; mt++)
#pragma unroll
        for (int nt = 0; nt < NT; nt++) mma_tf32(acc[mt][nt], af[mt], bf[nt]);
    }
    if (kt + 1 < KT) {
      __syncthreads();
      storeT(na, nb);
      __syncthreads();
    }
  }
  __syncthreads();

  float ps[4] = {0.f, 0.f, 0.f, 0.f};
#pragma unroll
  for (int nt = 0; nt < NT; nt++) {
#pragma unroll
    for (int j = 0; j < 2; j++) {
      int n = wn * 64 + nt * 8 + 2 * c + j;
      float bb = sBr[n], wp = sWp[n];
#pragma unroll
      for (int mt = 0; mt < MT; mt++) {
        float h0 = tanhf(acc[mt][nt][j] + bb);
        float h1 = tanhf(acc[mt][nt][2 + j] + bb);
        ps[mt * 2 + 0] = fmaf(h0, wp, ps[mt * 2 + 0]);
        ps[mt * 2 + 1] = fmaf(h1, wp, ps[mt * 2 + 1]);
      }
    }
  }
#pragma unroll
  for (int off = 1; off <= 2; off <<= 1)
#pragma unroll
    for (int i = 0; i < 4; i++) ps[i] += __shfl_xor_sync(0xffffffffu, ps[i], off);
  if (c == 0) {
#pragma unroll
    for (int mt = 0; mt < MT; mt++)
#pragma unroll
      for (int hf = 0; hf < 2; hf++)
        red[wm * 32 + mt * 16 + r + hf * 8][wn] = ps[mt * 2 + hf];
  }
  __syncthreads();

  float per = 0.f, val = 0.f;
  if (tid < 128) {
    float p = bp[0] + red[tid][0] + red[tid][1];
    size_t row = (size_t)bm + tid;
    out_probs[row] = 1.f / (1.f + expf(-p));
    float tg = target[row];
    if (tg >= 0.f) {
      per = fmaxf(p, 0.f) - p * tg + log1pf(expf(-fabsf(p)));
      val = 1.f;
    }
  }
  __syncthreads();
  if (tid < 128) { sl[tid] = per; sv[tid] = val; }
  __syncthreads();
  for (int s = 64; s > 0; s >>= 1) {
    if (tid < s) { sl[tid] += sl[tid + s]; sv[tid] += sv[tid + s]; }
    __syncthreads();
  }
  if (tid == 0) {
    g_part[2 * blockIdx.y] = sl[0];
    g_part[2 * blockIdx.y + 1] = sv[0];
  }
}

// ---------------- final loss reduction ----------------
__global__ void __launch_bounds__(256) finalize_kernel(float* __restrict__ out) {
  __shared__ float sl[256], sv[256];
  int tid = threadIdx.x;
  float l = 0.f, v = 0.f;
  for (int i = tid; i < BT_ / 128; i += 256) {
    l += g_part[2 * i];
    v += g_part[2 * i + 1];
  }
  sl[tid] = l; sv[tid] = v;
  __syncthreads();
  for (int s = 128; s > 0; s >>= 1) {
    if (tid < s) { sl[tid] += sl[tid + s]; sv[tid] += sv[tid + s]; }
    __syncthreads();
  }
  if (tid == 0) out[0] = sl[0] / fmaxf(sv[0], 1.f);
}

// ---------------- launch ----------------
extern "C" void kernel_launch(void* const* d_in, const int* in_sizes, int n_in,
                              void* d_out, int out_size) {
  const int* q_data = (const int*)d_in[0];
  const int* qa_data = (const int*)d_in[1];
  const float* target = (const float*)d_in[2];
  const float* q_tab = (const float*)d_in[3];
  const float* qa_tab = (const float*)d_in[4];
  const float* Mk = (const float*)d_in[5];
  const float* Mv0 = (const float*)d_in[6];
  const float* We = (const float*)d_in[7];
  const float* be = (const float*)d_in[8];
  const float* Wa = (const float*)d_in[9];
  const float* ba = (const float*)d_in[10];
  const float* Wr = (const float*)d_in[11];
  const float* br = (const float*)d_in[12];
  const float* Wp = (const float*)d_in[13];
  const float* bp = (const float*)d_in[14];
  float* out = (float*)d_out;

  logits_softmax_bf16<<<BT_ / 128, 256>>>(q_tab, q_data, Mk);
  gemm_ea_bf16<<<dim3(4, BT_ / 128), 256>>>(qa_tab, qa_data, We, be, Wa, ba);
  scan_kernel<<<B_, 256>>>(Mv0, q_data);
  final_tf32<<<dim3(1, BT_ / 128), 256>>>(q_tab, q_data, Wr, br, Wp, bp, target,
                                          out + 1);
  finalize_kernel<<<1, 256>>>(out);
}